// round 1
// baseline (speedup 1.0000x reference)
#include <cuda_runtime.h>
#include <math.h>

#define D_MODEL 256
#define D_INNER 512
#define D_STATE 16
#define D_CONV  4
#define DT_RANK 16
#define NB      16
#define NL      1024
#define NTOK    (NB * NL)          // 16384
#define DBC     (DT_RANK + 2 * D_STATE)  // 48

// ---------------- scratch (static device arrays; no allocation) -------------
__device__ float g_xz   [(size_t)NTOK * 2 * D_INNER]; // 64 MB  in_proj output
__device__ float g_xact [(size_t)NTOK * D_INNER];     // 32 MB  conv+silu output
__device__ float g_dbc  [(size_t)NTOK * DBC];         // 3 MB   x_proj output
__device__ float g_delta[(size_t)NTOK * D_INNER];     // 32 MB  softplus(dt_proj)
__device__ float g_y    [(size_t)NTOK * D_INNER];     // 32 MB  scan output (gated)

// ---------------- SGEMM: C[M,N] = A[M,K] @ W[N,K]^T  (fp32) -----------------
#define BM 128
#define BN 64
#define BKT 16

__global__ __launch_bounds__(256) void sgemm_nt(const float* __restrict__ A,
                                                const float* __restrict__ W,
                                                float* __restrict__ C,
                                                int M, int N, int K)
{
    __shared__ float As[BKT][BM + 4];
    __shared__ float Ws[BKT][BN + 4];
    const int tid = threadIdx.x;
    const int m0 = blockIdx.x * BM;
    const int n0 = blockIdx.y * BN;
    const int ty = tid >> 4;   // 0..15 -> 8 rows each
    const int tx = tid & 15;   // 0..15 -> 4 cols each
    const int lr = tid >> 2;   // 0..63
    const int lc = tid & 3;    // 0..3

    float acc[8][4];
#pragma unroll
    for (int i = 0; i < 8; i++)
#pragma unroll
        for (int j = 0; j < 4; j++) acc[i][j] = 0.f;

    for (int k0 = 0; k0 < K; k0 += BKT) {
        // load A tile 128x16 (M assumed multiple of 128; true for all calls)
#pragma unroll
        for (int r = 0; r < 2; r++) {
            float4 v = *(const float4*)(A + (size_t)(m0 + lr + r * 64) * K + k0 + lc * 4);
            As[lc * 4 + 0][lr + r * 64] = v.x;
            As[lc * 4 + 1][lr + r * 64] = v.y;
            As[lc * 4 + 2][lr + r * 64] = v.z;
            As[lc * 4 + 3][lr + r * 64] = v.w;
        }
        // load W tile 64x16 (guard rows for N=48 case)
        {
            float4 v = make_float4(0.f, 0.f, 0.f, 0.f);
            if (n0 + lr < N)
                v = *(const float4*)(W + (size_t)(n0 + lr) * K + k0 + lc * 4);
            Ws[lc * 4 + 0][lr] = v.x;
            Ws[lc * 4 + 1][lr] = v.y;
            Ws[lc * 4 + 2][lr] = v.z;
            Ws[lc * 4 + 3][lr] = v.w;
        }
        __syncthreads();
#pragma unroll
        for (int k = 0; k < BKT; k++) {
            float4 a0 = *(const float4*)&As[k][ty * 8];
            float4 a1 = *(const float4*)&As[k][ty * 8 + 4];
            float4 b  = *(const float4*)&Ws[k][tx * 4];
            float av[8] = {a0.x, a0.y, a0.z, a0.w, a1.x, a1.y, a1.z, a1.w};
            float bv[4] = {b.x, b.y, b.z, b.w};
#pragma unroll
            for (int i = 0; i < 8; i++)
#pragma unroll
                for (int j = 0; j < 4; j++)
                    acc[i][j] = fmaf(av[i], bv[j], acc[i][j]);
        }
        __syncthreads();
    }
#pragma unroll
    for (int i = 0; i < 8; i++) {
        size_t row = (size_t)(m0 + ty * 8 + i) * N;
#pragma unroll
        for (int j = 0; j < 4; j++) {
            int n = n0 + tx * 4 + j;
            if (n < N) C[row + n] = acc[i][j];
        }
    }
}

// ---------------- depthwise causal conv1d + SiLU -----------------------------
__global__ __launch_bounds__(256) void conv_silu(const float* __restrict__ conv_w,
                                                 const float* __restrict__ conv_b)
{
    int gid = blockIdx.x * blockDim.x + threadIdx.x;
    if (gid >= NTOK * D_INNER) return;
    int d = gid & (D_INNER - 1);
    int m = gid >> 9;          // token index b*NL + l
    int l = m & (NL - 1);
    float acc = conv_b[d];
#pragma unroll
    for (int k = 0; k < D_CONV; k++) {
        int off = k - (D_CONV - 1);
        if (l + off >= 0)
            acc = fmaf(conv_w[d * D_CONV + k],
                       g_xz[(size_t)(m + off) * (2 * D_INNER) + d], acc);
    }
    float s = 1.f / (1.f + __expf(-acc));
    g_xact[gid] = acc * s;
}

// ---------------- dt_proj + softplus ----------------------------------------
#define DT_MROWS 8
__global__ __launch_bounds__(512) void dtproj_softplus(const float* __restrict__ dtw,
                                                       const float* __restrict__ dtb)
{
    __shared__ float sdt[DT_MROWS][DT_RANK];
    int d = threadIdx.x;                 // 0..511, one inner channel per thread
    int mbase = blockIdx.x * DT_MROWS;

    float w[DT_RANK];
    const float4* wp = (const float4*)(dtw + (size_t)d * DT_RANK);
#pragma unroll
    for (int q = 0; q < 4; q++) {
        float4 v = wp[q];
        w[q * 4 + 0] = v.x; w[q * 4 + 1] = v.y;
        w[q * 4 + 2] = v.z; w[q * 4 + 3] = v.w;
    }
    float bias = dtb[d];

    if (d < DT_MROWS * DT_RANK)
        sdt[d / DT_RANK][d % DT_RANK] =
            g_dbc[(size_t)(mbase + d / DT_RANK) * DBC + (d % DT_RANK)];
    __syncthreads();

#pragma unroll
    for (int mi = 0; mi < DT_MROWS; mi++) {
        float v = bias;
#pragma unroll
        for (int r = 0; r < DT_RANK; r++) v = fmaf(sdt[mi][r], w[r], v);
        float sp = (v > 20.f) ? v : log1pf(__expf(v));
        g_delta[(size_t)(mbase + mi) * D_INNER + d] = sp;
    }
}

// ---------------- selective scan + skip + gating -----------------------------
// 1 warp = 2 (b,d) channels; 16 lanes per channel = 16 states.
__global__ __launch_bounds__(256) void selective_scan(const float* __restrict__ A_log,
                                                      const float* __restrict__ D_skip)
{
    int t = blockIdx.x * blockDim.x + threadIdx.x;
    int warp = t >> 5;
    int lane = t & 31;
    int n = lane & 15;                 // state index
    int p = warp * 2 + (lane >> 4);    // channel-pair index 0..8191
    int b = p >> 9;
    int d = p & (D_INNER - 1);

    float a  = -expf(A_log[d * D_STATE + n]);   // A[d][n] < 0
    float Dd = D_skip[d];
    float h = 0.f;
    int mbase = b * NL;

#pragma unroll 2
    for (int l = 0; l < NL; l++) {
        int m = mbase + l;
        float delta = __ldg(&g_delta[(size_t)m * D_INNER + d]);
        float xv    = __ldg(&g_xact [(size_t)m * D_INNER + d]);
        float zv    = __ldg(&g_xz   [(size_t)m * (2 * D_INNER) + D_INNER + d]);
        float Bv    = __ldg(&g_dbc  [(size_t)m * DBC + DT_RANK + n]);
        float Cv    = __ldg(&g_dbc  [(size_t)m * DBC + DT_RANK + D_STATE + n]);

        float dA = __expf(delta * a);
        h = fmaf(dA, h, delta * Bv * xv);

        float yp = h * Cv;
#pragma unroll
        for (int o = 8; o >= 1; o >>= 1)
            yp += __shfl_xor_sync(0xffffffffu, yp, o);

        if (n == 0) {
            float yv = fmaf(xv, Dd, yp);
            float sz = zv / (1.f + __expf(-zv));
            g_y[(size_t)m * D_INNER + d] = yv * sz;
        }
    }
}

// ---------------- launch ------------------------------------------------------
extern "C" void kernel_launch(void* const* d_in, const int* in_sizes, int n_in,
                              void* d_out, int out_size)
{
    const float* token   = (const float*)d_in[0];
    const float* in_w    = (const float*)d_in[1];
    const float* conv_w  = (const float*)d_in[2];
    const float* conv_b  = (const float*)d_in[3];
    const float* xproj_w = (const float*)d_in[4];
    const float* dt_w    = (const float*)d_in[5];
    const float* dt_b    = (const float*)d_in[6];
    const float* A_log   = (const float*)d_in[7];
    const float* D_skip  = (const float*)d_in[8];
    const float* out_w   = (const float*)d_in[9];
    float* out = (float*)d_out;

    float *xz, *xact, *dbc, *y;
    cudaGetSymbolAddress((void**)&xz,   g_xz);
    cudaGetSymbolAddress((void**)&xact, g_xact);
    cudaGetSymbolAddress((void**)&dbc,  g_dbc);
    cudaGetSymbolAddress((void**)&y,    g_y);

    // 1. in_proj: xz[16384,1024] = token @ in_w^T
    sgemm_nt<<<dim3(NTOK / BM, (2 * D_INNER) / BN), 256>>>(
        token, in_w, xz, NTOK, 2 * D_INNER, D_MODEL);

    // 2. depthwise conv + silu -> xact
    conv_silu<<<(NTOK * D_INNER) / 256, 256>>>(conv_w, conv_b);

    // 3. x_proj: dbc[16384,48] = xact @ xproj_w^T
    sgemm_nt<<<dim3(NTOK / BM, (DBC + BN - 1) / BN), 256>>>(
        xact, xproj_w, dbc, NTOK, DBC, D_INNER);

    // 4. dt_proj + softplus -> delta
    dtproj_softplus<<<NTOK / DT_MROWS, 512>>>(dt_w, dt_b);

    // 5. selective scan + skip + gate -> y
    selective_scan<<<(NB * D_INNER / 2) / 8, 256>>>(A_log, D_skip);

    // 6. out_proj: out[16384,256] = y @ out_w^T
    sgemm_nt<<<dim3(NTOK / BM, D_MODEL / BN), 256>>>(
        y, out_w, out, NTOK, D_MODEL, D_INNER);
}